// round 14
// baseline (speedup 1.0000x reference)
#include <cuda_runtime.h>
#include <cuda_bf16.h>
#include <math.h>
#include <stdint.h>

#define B 2
#define C 256
#define ZS 32
#define HW 2304
#define DHW 73728
#define CDHW 18874368
#define TOT 37748736
#define HP 6
#define NTOT 147456
#define NROWS 147456   // B*ZS*HW

// GEMM smem: per stage 4 tiles of 128 rows x 64 bf16, padded to 72 elems/row
#define SPITCH 72
#define TILEB (128 * SPITCH * 2)     // 18432 bytes
#define STAGEB (4 * TILEB)           // 73728 bytes
#define DYN_SMEM (2 * STAGEB)        // 147456 bytes

// ---------------- scratch (no allocations allowed) ----------------
__device__ float g_v[TOT];                    // u = W·x
__device__ __nv_bfloat16 g_ahi[512 * C];      // rows 0-255: o_w@v_w, 256-511: q_w
__device__ __nv_bfloat16 g_alo[512 * C];
__device__ __nv_bfloat16 g_bhi[(size_t)NROWS * C]; // x transposed (slice,hw,c)
__device__ __nv_bfloat16 g_blo[(size_t)NROWS * C];
__device__ float g_pe[ZS * C];
__device__ float g_qp[B * ZS * C];
__device__ float g_M[B * ZS * ZS];
__device__ float g_sum[C];
__device__ float g_sumsq[C];
__device__ float g_scale[C];
__device__ float g_shift[C];

__device__ __forceinline__ uint32_t smem_u32(const void* p) {
    uint32_t a;
    asm("{ .reg .u64 t; cvta.to.shared.u64 t, %1; cvt.u32.u64 %0, t; }" : "=r"(a) : "l"(p));
    return a;
}

__device__ __forceinline__ void cpasync16(uint32_t dst, const void* src) {
    asm volatile("cp.async.cg.shared.global [%0], [%1], 16;" :: "r"(dst), "l"(src));
}

__device__ __forceinline__ void ldsm4(uint32_t& r0, uint32_t& r1, uint32_t& r2, uint32_t& r3,
                                      uint32_t addr) {
    asm volatile("ldmatrix.sync.aligned.m8n8.x4.shared.b16 {%0,%1,%2,%3}, [%4];"
                 : "=r"(r0), "=r"(r1), "=r"(r2), "=r"(r3) : "r"(addr));
}

__device__ __forceinline__ void mma16816(float* d, const uint32_t* a, const uint32_t* b) {
    asm volatile(
        "mma.sync.aligned.m16n8k16.row.col.f32.bf16.bf16.f32 "
        "{%0,%1,%2,%3}, {%4,%5,%6,%7}, {%8,%9}, {%0,%1,%2,%3};"
        : "+f"(d[0]), "+f"(d[1]), "+f"(d[2]), "+f"(d[3])
        : "r"(a[0]), "r"(a[1]), "r"(a[2]), "r"(a[3]), "r"(b[0]), "r"(b[1]));
}

__device__ __forceinline__ void atomicMaxFloat(float* addr, float val) {
    int* ia = (int*)addr;
    int old = *ia;
    while (__int_as_float(old) < val) {
        int prev = atomicCAS(ia, old, __float_as_int(val));
        if (prev == old) break;
        old = prev;
    }
}

// ---------------- init ----------------
__global__ void k_init() {
    int i = blockIdx.x * blockDim.x + threadIdx.x;
    if (i < B * ZS * C) g_qp[i] = -3.402823466e38f;
    if (i < ZS * C) {
        int d = i / C, c = i % C;
        int ii = c >> 1;
        float ang = (float)d * expf(-0.0719557841560637f * (float)ii);
        g_pe[i] = (c & 1) ? cosf(ang) : sinf(ang);
    }
    if (i < C) { g_sum[i] = 0.f; g_sumsq[i] = 0.f; }
}

// ---------------- fold W = o_w@v_w, stack q_w, split bf16 hi/lo ----------------
__launch_bounds__(256)
__global__ void k_wsplit(const float* __restrict__ o_w, const float* __restrict__ v_w,
                         const float* __restrict__ q_w) {
    __shared__ float orow[C];
    int r = blockIdx.x, c = threadIdx.x;
    float val;
    if (r < 256) {
        orow[c] = o_w[r * C + c];
        __syncthreads();
        float acc = 0.f;
#pragma unroll 8
        for (int k = 0; k < C; k++) acc += orow[k] * v_w[k * C + c];
        val = acc;
    } else {
        val = q_w[(r - 256) * C + c];
    }
    __nv_bfloat16 h = __float2bfloat16(val);
    g_ahi[r * C + c] = h;
    g_alo[r * C + c] = __float2bfloat16(val - __bfloat162float(h));
}

// ---------------- x = feat + pe, transpose to (slice,hw,c), split hi/lo ----------------
__launch_bounds__(256)
__global__ void k_xsplit(const float* __restrict__ feat) {
    __shared__ __nv_bfloat16 shi[C][33];
    __shared__ __nv_bfloat16 slo[C][33];
    int blk = blockIdx.x;
    int sl = blk / 72, tile = blk % 72;
    int b = sl >> 5, d = sl & 31;
    int hw0 = tile * 32;
    int t = threadIdx.x, lane = t & 31, w = t >> 5;
    const float* fb = feat + (size_t)b * CDHW + (size_t)d * HW + hw0 + lane;
#pragma unroll 4
    for (int cc = 0; cc < 32; cc++) {
        int c = cc * 8 + w;
        float v = fb[(size_t)c * DHW] + g_pe[d * C + c];
        __nv_bfloat16 h = __float2bfloat16(v);
        shi[c][lane] = h;
        slo[c][lane] = __float2bfloat16(v - __bfloat162float(h));
    }
    __syncthreads();
    int row = t >> 3, seg = t & 7;
    size_t n = (size_t)sl * HW + hw0 + row;
#pragma unroll
    for (int q = 0; q < 4; q++) {
        int c0 = (q * 8 + seg) * 8;
        union { __nv_bfloat16 v[8]; uint4 u; } ph, pl;
#pragma unroll
        for (int j = 0; j < 8; j++) { ph.v[j] = shi[c0 + j][row]; pl.v[j] = slo[c0 + j][row]; }
        *(uint4*)(g_bhi + n * C + c0) = ph.u;
        *(uint4*)(g_blo + n * C + c0) = pl.u;
    }
}

// ---------------- bf16 mma.sync GEMM, cp.async 2-stage, 16 warps ----------------
// grid (4 mb, 18 ntiles, 64 slices), 512 thr. warp grid 4m x 4n, warp tile 32x32.
// mb 0,1 -> u (g_v); mb 2,3 -> q (max into g_qp).
__global__ void __launch_bounds__(512) k_gemm() {
    extern __shared__ char sm[];
    uint32_t smb = smem_u32(sm);

    int tid = threadIdx.x, lane = tid & 31, wid = tid >> 5;
    int mb = blockIdx.x, ntile = blockIdx.y, sl = blockIdx.z;
    int b = sl >> 5, d = sl & 31;
    int mwarp = (wid >> 2) * 32;
    int nwarp = (wid & 3) * 32;

    size_t arow0 = (size_t)mb * 128;
    size_t nrow0 = (size_t)sl * HW + (size_t)ntile * 128;

    float acc[2][4][4];
#pragma unroll
    for (int mf = 0; mf < 2; mf++)
#pragma unroll
        for (int nf = 0; nf < 4; nf++)
#pragma unroll
            for (int e = 0; e < 4; e++) acc[mf][nf][e] = 0.f;

    // ldmatrix source byte offsets within a tile
    uint32_t aoff = (uint32_t)((mwarp + (lane & 15)) * SPITCH + ((lane >> 4) << 3)) * 2;
    uint32_t boff0 = (uint32_t)((nwarp + (lane & 7) + ((lane >> 4) << 3)) * SPITCH
                                + (((lane >> 3) & 1) << 3)) * 2;

    // async chunk loader: chunk ch (k0 = ch*64) into stage st
    auto load_chunk = [&](int ch, int st) {
        int k0 = ch * 64;
        uint32_t sb = smb + (uint32_t)st * STAGEB;
#pragma unroll
        for (int i = 0; i < 2; i++) {
            int idx = tid + 512 * i;
            int r = idx >> 3, cc = idx & 7;
            uint32_t so = (uint32_t)(r * SPITCH + cc * 8) * 2;
            const __nv_bfloat16* pa = g_ahi + (arow0 + r) * C + k0 + cc * 8;
            const __nv_bfloat16* pb = g_alo + (arow0 + r) * C + k0 + cc * 8;
            const __nv_bfloat16* pc = g_bhi + (nrow0 + r) * C + k0 + cc * 8;
            const __nv_bfloat16* pd = g_blo + (nrow0 + r) * C + k0 + cc * 8;
            cpasync16(sb + so, pa);
            cpasync16(sb + TILEB + so, pb);
            cpasync16(sb + 2 * TILEB + so, pc);
            cpasync16(sb + 3 * TILEB + so, pd);
        }
        asm volatile("cp.async.commit_group;");
    };

    load_chunk(0, 0);

    for (int ch = 0; ch < 4; ch++) {
        int st = ch & 1;
        if (ch < 3) {
            load_chunk(ch + 1, st ^ 1);
            asm volatile("cp.async.wait_group 1;");
        } else {
            asm volatile("cp.async.wait_group 0;");
        }
        __syncthreads();

        uint32_t sb = smb + (uint32_t)st * STAGEB;
#pragma unroll
        for (int ks = 0; ks < 4; ks++) {
            uint32_t kso = (uint32_t)(ks * 16) * 2;
            uint32_t bh[4][2], bl[4][2];
#pragma unroll
            for (int nf2 = 0; nf2 < 2; nf2++) {
                uint32_t ba = sb + 2 * TILEB + boff0 + (uint32_t)(nf2 * 16 * SPITCH) * 2 + kso;
                ldsm4(bh[nf2 * 2][0], bh[nf2 * 2][1], bh[nf2 * 2 + 1][0], bh[nf2 * 2 + 1][1], ba);
                uint32_t bb = sb + 3 * TILEB + boff0 + (uint32_t)(nf2 * 16 * SPITCH) * 2 + kso;
                ldsm4(bl[nf2 * 2][0], bl[nf2 * 2][1], bl[nf2 * 2 + 1][0], bl[nf2 * 2 + 1][1], bb);
            }
#pragma unroll
            for (int mf = 0; mf < 2; mf++) {
                uint32_t ah[4], al[4];
                uint32_t aa = sb + aoff + (uint32_t)(mf * 16 * SPITCH) * 2 + kso;
                ldsm4(ah[0], ah[1], ah[2], ah[3], aa);
                uint32_t ab = sb + TILEB + aoff + (uint32_t)(mf * 16 * SPITCH) * 2 + kso;
                ldsm4(al[0], al[1], al[2], al[3], ab);
#pragma unroll
                for (int nf = 0; nf < 4; nf++) {
                    mma16816(acc[mf][nf], ah, bh[nf]);
                    mma16816(acc[mf][nf], ah, bl[nf]);
                    mma16816(acc[mf][nf], al, bh[nf]);
                }
            }
        }
        __syncthreads();
    }

    int hw0 = ntile * 128;
    if (mb < 2) {
#pragma unroll
        for (int mf = 0; mf < 2; mf++) {
            int m0 = mb * 128 + mwarp + mf * 16 + (lane >> 2);
#pragma unroll
            for (int nf = 0; nf < 4; nf++) {
                int col = hw0 + nwarp + nf * 8 + (lane & 3) * 2;
                float* o0 = g_v + (size_t)b * CDHW + (size_t)m0 * DHW + (size_t)d * HW + col;
                float* o1 = g_v + (size_t)b * CDHW + (size_t)(m0 + 8) * DHW + (size_t)d * HW + col;
                *(float2*)o0 = make_float2(acc[mf][nf][0], acc[mf][nf][1]);
                *(float2*)o1 = make_float2(acc[mf][nf][2], acc[mf][nf][3]);
            }
        }
    } else {
#pragma unroll
        for (int mf = 0; mf < 2; mf++) {
            float mlo = -3.402823466e38f, mhi = -3.402823466e38f;
#pragma unroll
            for (int nf = 0; nf < 4; nf++) {
                mlo = fmaxf(mlo, fmaxf(acc[mf][nf][0], acc[mf][nf][1]));
                mhi = fmaxf(mhi, fmaxf(acc[mf][nf][2], acc[mf][nf][3]));
            }
#pragma unroll
            for (int off = 2; off >= 1; off >>= 1) {
                mlo = fmaxf(mlo, __shfl_xor_sync(0xffffffffu, mlo, off));
                mhi = fmaxf(mhi, __shfl_xor_sync(0xffffffffu, mhi, off));
            }
            if ((lane & 3) == 0) {
                int m0 = (mb - 2) * 128 + mwarp + mf * 16 + (lane >> 2);
                atomicMaxFloat(&g_qp[sl * C + m0], mlo);
                atomicMaxFloat(&g_qp[sl * C + m0 + 8], mhi);
            }
        }
    }
}

// ---------------- offsets / attention / mixing matrix M ----------------
__launch_bounds__(256)
__global__ void k_mrow(const float* __restrict__ offs_w,
                       const float* __restrict__ offs_b,
                       const float* __restrict__ attn_w,
                       const float* __restrict__ attn_b) {
    __shared__ float sh[12][8];
    int bz = blockIdx.x;
    int c = threadIdx.x;
    float q = g_qp[(size_t)bz * C + c];

    float po[HP], pl[HP];
#pragma unroll
    for (int p = 0; p < HP; p++) {
        po[p] = q * offs_w[p * C + c];
        pl[p] = q * attn_w[p * C + c];
    }
#pragma unroll
    for (int off = 16; off >= 1; off >>= 1) {
#pragma unroll
        for (int p = 0; p < HP; p++) {
            po[p] += __shfl_xor_sync(0xffffffffu, po[p], off);
            pl[p] += __shfl_xor_sync(0xffffffffu, pl[p], off);
        }
    }
    int lane = c & 31, wid = c >> 5;
    if (lane == 0) {
#pragma unroll
        for (int p = 0; p < HP; p++) { sh[p][wid] = po[p]; sh[HP + p][wid] = pl[p]; }
    }
    __syncthreads();
    if (c == 0) {
        float offv[HP], lg[HP];
#pragma unroll
        for (int p = 0; p < HP; p++) {
            float s1 = 0.f, s2 = 0.f;
#pragma unroll
            for (int w = 0; w < 8; w++) { s1 += sh[p][w]; s2 += sh[HP + p][w]; }
            offv[p] = s1 + offs_b[p];
            lg[p]   = s2 + attn_b[p];
        }
        float mx = lg[0];
#pragma unroll
        for (int p = 1; p < HP; p++) mx = fmaxf(mx, lg[p]);
        float s = 0.f;
#pragma unroll
        for (int p = 0; p < HP; p++) { lg[p] = expf(lg[p] - mx); s += lg[p]; }
        float inv = 1.f / s;

        float row[ZS];
#pragma unroll
        for (int y = 0; y < ZS; y++) row[y] = 0.f;
#pragma unroll
        for (int p = 0; p < HP; p++) {
            float o = fminf(fmaxf(offv[p], 0.f), (float)(ZS - 1));
            float lo = floorf(o), hi = ceilf(o);
            float fr = o - lo;
            float a = lg[p] * inv;
            row[(int)lo] += a * (1.f - fr);
            row[(int)hi] += a * fr;
        }
#pragma unroll
        for (int y = 0; y < ZS; y++) g_M[bz * ZS + y] = row[y];
    }
}

// ---------------- depth mixing -> d_out, fused BN partial stats ----------------
__launch_bounds__(256)
__global__ void k_mix_stats(float* __restrict__ out) {
    __shared__ float Ms[ZS * ZS];
    __shared__ float red1[8], red2[8];
    int t = blockIdx.x * 256 + threadIdx.x;
    int b = (blockIdx.x * 256) / (C * HW);
    for (int i = threadIdx.x; i < ZS * ZS; i += 256)
        Ms[i] = g_M[b * ZS * ZS + i];
    __syncthreads();

    int rem = t % (C * HW);
    int c = rem / HW, hw = rem % HW;
    const float* base = g_v + (size_t)b * CDHW + (size_t)c * DHW + hw;
    float* ob = out + (size_t)b * CDHW + (size_t)c * DHW + hw;
    float v[ZS];
#pragma unroll
    for (int y = 0; y < ZS; y++) v[y] = base[(size_t)y * HW];
    float s1 = 0.f, s2 = 0.f;
#pragma unroll
    for (int z = 0; z < ZS; z++) {
        float a = 0.f;
#pragma unroll
        for (int y = 0; y < ZS; y++) a += Ms[z * ZS + y] * v[y];
        ob[(size_t)z * HW] = a;
        s1 += a; s2 += a * a;
    }
#pragma unroll
    for (int off = 16; off >= 1; off >>= 1) {
        s1 += __shfl_xor_sync(0xffffffffu, s1, off);
        s2 += __shfl_xor_sync(0xffffffffu, s2, off);
    }
    int lane = threadIdx.x & 31, wid = threadIdx.x >> 5;
    if (lane == 0) { red1[wid] = s1; red2[wid] = s2; }
    __syncthreads();
    if (threadIdx.x < 8) {
        s1 = red1[threadIdx.x]; s2 = red2[threadIdx.x];
#pragma unroll
        for (int off = 4; off >= 1; off >>= 1) {
            s1 += __shfl_xor_sync(0xffu, s1, off);
            s2 += __shfl_xor_sync(0xffu, s2, off);
        }
        if (threadIdx.x == 0) {
            atomicAdd(&g_sum[c], s1);
            atomicAdd(&g_sumsq[c], s2);
        }
    }
}

// ---------------- finalize BN scale/shift ----------------
__global__ void k_stats(const float* __restrict__ gamma,
                        const float* __restrict__ beta) {
    int o = threadIdx.x;
    if (o >= C) return;
    float cnt = (float)NTOT;
    float mean = g_sum[o] / cnt;
    float var = g_sumsq[o] / cnt - mean * mean;
    float inv = rsqrtf(var + 1e-5f);
    g_scale[o] = inv * gamma[o];
    g_shift[o] = beta[o] - mean * inv * gamma[o];
}

// ---------------- BN apply + residual, in place on out ----------------
__launch_bounds__(256)
__global__ void k_apply(const float* __restrict__ feat, float* __restrict__ out) {
    size_t i = ((size_t)blockIdx.x * 256 + threadIdx.x) * 4;
    if (i >= (size_t)TOT) return;
    int c = (int)((i / DHW) % C);
    float sc = g_scale[c], sh = g_shift[c];
    float4 p = *(float4*)(out + i);
    float4 f = *(const float4*)(feat + i);
    p.x = p.x * sc + sh + f.x;
    p.y = p.y * sc + sh + f.y;
    p.z = p.z * sc + sh + f.z;
    p.w = p.w * sc + sh + f.w;
    *(float4*)(out + i) = p;
}

extern "C" void kernel_launch(void* const* d_in, const int* in_sizes, int n_in,
                              void* d_out, int out_size) {
    const float* feat   = (const float*)d_in[0];
    const float* q_w    = (const float*)d_in[1];
    const float* v_w    = (const float*)d_in[2];
    const float* o_w    = (const float*)d_in[3];
    const float* offs_w = (const float*)d_in[4];
    const float* offs_b = (const float*)d_in[5];
    const float* attn_w = (const float*)d_in[6];
    const float* attn_b = (const float*)d_in[7];
    const float* gamma  = (const float*)d_in[8];
    const float* beta   = (const float*)d_in[9];
    float* out = (float*)d_out;

    cudaFuncSetAttribute(k_gemm, cudaFuncAttributeMaxDynamicSharedMemorySize, DYN_SMEM);

    k_init<<<64, 256>>>();
    k_wsplit<<<512, 256>>>(o_w, v_w, q_w);
    k_xsplit<<<4608, 256>>>(feat);
    k_gemm<<<dim3(4, 18, 64), 512, DYN_SMEM>>>();
    k_mrow<<<64, 256>>>(offs_w, offs_b, attn_w, attn_b);
    k_mix_stats<<<4608, 256>>>(out);
    k_stats<<<1, 256>>>(gamma, beta);
    k_apply<<<36864, 256>>>(feat, out);
}

// round 15
// speedup vs baseline: 1.3510x; 1.3510x over previous
#include <cuda_runtime.h>
#include <cuda_bf16.h>
#include <math.h>
#include <stdint.h>

#define B 2
#define C 256
#define ZS 32
#define HW 2304
#define DHW 73728
#define CDHW 18874368
#define TOT 37748736
#define HP 6
#define NTOT 147456
#define NROWS 147456   // B*ZS*HW

// GEMM smem: per stage 4 tiles of 128 rows x 64 bf16, padded to 72 elems/row
#define SPITCH 72
#define TILEB (128 * SPITCH * 2)     // 18432 bytes
#define STAGEB (4 * TILEB)           // 73728 bytes
#define DYN_SMEM (2 * STAGEB)        // 147456 bytes

// ---------------- scratch (no allocations allowed) ----------------
__device__ float g_v[TOT];                    // u = W·x
__device__ __nv_bfloat16 g_ahi[512 * C];      // rows 0-255: o_w@v_w, 256-511: q_w
__device__ __nv_bfloat16 g_alo[512 * C];
__device__ __nv_bfloat16 g_bhi[(size_t)NROWS * C]; // x transposed (slice,hw,c)
__device__ __nv_bfloat16 g_blo[(size_t)NROWS * C];
__device__ float g_pe[ZS * C];
__device__ float g_qp[B * ZS * C];
__device__ float g_M[B * ZS * ZS];
__device__ float g_sum[C];
__device__ float g_sumsq[C];
__device__ float g_scale[C];
__device__ float g_shift[C];

__device__ __forceinline__ uint32_t smem_u32(const void* p) {
    uint32_t a;
    asm("{ .reg .u64 t; cvta.to.shared.u64 t, %1; cvt.u32.u64 %0, t; }" : "=r"(a) : "l"(p));
    return a;
}

__device__ __forceinline__ void cpasync16(uint32_t dst, const void* src) {
    asm volatile("cp.async.cg.shared.global [%0], [%1], 16;" :: "r"(dst), "l"(src));
}

__device__ __forceinline__ void ldsm4(uint32_t& r0, uint32_t& r1, uint32_t& r2, uint32_t& r3,
                                      uint32_t addr) {
    asm volatile("ldmatrix.sync.aligned.m8n8.x4.shared.b16 {%0,%1,%2,%3}, [%4];"
                 : "=r"(r0), "=r"(r1), "=r"(r2), "=r"(r3) : "r"(addr));
}

__device__ __forceinline__ void mma16816(float* d, const uint32_t* a, const uint32_t* b) {
    asm volatile(
        "mma.sync.aligned.m16n8k16.row.col.f32.bf16.bf16.f32 "
        "{%0,%1,%2,%3}, {%4,%5,%6,%7}, {%8,%9}, {%0,%1,%2,%3};"
        : "+f"(d[0]), "+f"(d[1]), "+f"(d[2]), "+f"(d[3])
        : "r"(a[0]), "r"(a[1]), "r"(a[2]), "r"(a[3]), "r"(b[0]), "r"(b[1]));
}

__device__ __forceinline__ void atomicMaxFloat(float* addr, float val) {
    int* ia = (int*)addr;
    int old = *ia;
    while (__int_as_float(old) < val) {
        int prev = atomicCAS(ia, old, __float_as_int(val));
        if (prev == old) break;
        old = prev;
    }
}

// ---------------- init ----------------
__global__ void k_init() {
    int i = blockIdx.x * blockDim.x + threadIdx.x;
    if (i < B * ZS * C) g_qp[i] = -3.402823466e38f;
    if (i < ZS * C) {
        int d = i / C, c = i % C;
        int ii = c >> 1;
        float ang = (float)d * expf(-0.0719557841560637f * (float)ii);
        g_pe[i] = (c & 1) ? cosf(ang) : sinf(ang);
    }
    if (i < C) { g_sum[i] = 0.f; g_sumsq[i] = 0.f; }
}

// ---------------- fold W = o_w@v_w, stack q_w, split bf16 hi/lo ----------------
__launch_bounds__(256)
__global__ void k_wsplit(const float* __restrict__ o_w, const float* __restrict__ v_w,
                         const float* __restrict__ q_w) {
    __shared__ float orow[C];
    int r = blockIdx.x, c = threadIdx.x;
    float val;
    if (r < 256) {
        orow[c] = o_w[r * C + c];
        __syncthreads();
        float acc = 0.f;
#pragma unroll 8
        for (int k = 0; k < C; k++) acc += orow[k] * v_w[k * C + c];
        val = acc;
    } else {
        val = q_w[(r - 256) * C + c];
    }
    __nv_bfloat16 h = __float2bfloat16(val);
    g_ahi[r * C + c] = h;
    g_alo[r * C + c] = __float2bfloat16(val - __bfloat162float(h));
}

// ---------------- x = feat + pe, transpose to (slice,hw,c), split hi/lo ----------------
__launch_bounds__(256)
__global__ void k_xsplit(const float* __restrict__ feat) {
    __shared__ __nv_bfloat16 shi[C][33];
    __shared__ __nv_bfloat16 slo[C][33];
    int blk = blockIdx.x;
    int sl = blk / 72, tile = blk % 72;
    int b = sl >> 5, d = sl & 31;
    int hw0 = tile * 32;
    int t = threadIdx.x, lane = t & 31, w = t >> 5;
    const float* fb = feat + (size_t)b * CDHW + (size_t)d * HW + hw0 + lane;
#pragma unroll 4
    for (int cc = 0; cc < 32; cc++) {
        int c = cc * 8 + w;
        float v = fb[(size_t)c * DHW] + g_pe[d * C + c];
        __nv_bfloat16 h = __float2bfloat16(v);
        shi[c][lane] = h;
        slo[c][lane] = __float2bfloat16(v - __bfloat162float(h));
    }
    __syncthreads();
    int row = t >> 3, seg = t & 7;
    size_t n = (size_t)sl * HW + hw0 + row;
#pragma unroll
    for (int q = 0; q < 4; q++) {
        int c0 = (q * 8 + seg) * 8;
        union { __nv_bfloat16 v[8]; uint4 u; } ph, pl;
#pragma unroll
        for (int j = 0; j < 8; j++) { ph.v[j] = shi[c0 + j][row]; pl.v[j] = slo[c0 + j][row]; }
        *(uint4*)(g_bhi + n * C + c0) = ph.u;
        *(uint4*)(g_blo + n * C + c0) = pl.u;
    }
}

// ---------------- bf16 mma.sync GEMM, cp.async 2-stage, term-major MMA ----------------
// grid (4 mb, 18 ntiles, 64 slices), 256 thr, warp tile 64x32.
// mb 0,1 -> u (g_v); mb 2,3 -> q (max into g_qp).
__global__ void __launch_bounds__(256) k_gemm() {
    extern __shared__ char sm[];
    uint32_t smb = smem_u32(sm);

    int tid = threadIdx.x, lane = tid & 31, wid = tid >> 5;
    int mb = blockIdx.x, ntile = blockIdx.y, sl = blockIdx.z;
    int b = sl >> 5, d = sl & 31;
    int mwarp = (wid >> 2) * 64;
    int nwarp = (wid & 3) * 32;

    size_t arow0 = (size_t)mb * 128;
    size_t nrow0 = (size_t)sl * HW + (size_t)ntile * 128;

    float acc[4][4][4];
#pragma unroll
    for (int mf = 0; mf < 4; mf++)
#pragma unroll
        for (int nf = 0; nf < 4; nf++)
#pragma unroll
            for (int e = 0; e < 4; e++) acc[mf][nf][e] = 0.f;

    // ldmatrix source byte offsets within a tile
    uint32_t aoff = (uint32_t)((mwarp + (lane & 15)) * SPITCH + ((lane >> 4) << 3)) * 2;
    uint32_t boff0 = (uint32_t)((nwarp + (lane & 7) + ((lane >> 4) << 3)) * SPITCH
                                + (((lane >> 3) & 1) << 3)) * 2;

    // async chunk loader: chunk ch (k0 = ch*64) into stage st
    auto load_chunk = [&](int ch, int st) {
        int k0 = ch * 64;
        uint32_t sb = smb + (uint32_t)st * STAGEB;
#pragma unroll
        for (int i = 0; i < 4; i++) {
            int idx = tid + 256 * i;
            int r = idx >> 3, cc = idx & 7;
            uint32_t so = (uint32_t)(r * SPITCH + cc * 8) * 2;
            const __nv_bfloat16* pa = g_ahi + (arow0 + r) * C + k0 + cc * 8;
            const __nv_bfloat16* pb = g_alo + (arow0 + r) * C + k0 + cc * 8;
            const __nv_bfloat16* pc = g_bhi + (nrow0 + r) * C + k0 + cc * 8;
            const __nv_bfloat16* pd = g_blo + (nrow0 + r) * C + k0 + cc * 8;
            cpasync16(sb + so, pa);
            cpasync16(sb + TILEB + so, pb);
            cpasync16(sb + 2 * TILEB + so, pc);
            cpasync16(sb + 3 * TILEB + so, pd);
        }
        asm volatile("cp.async.commit_group;");
    };

    load_chunk(0, 0);

    for (int ch = 0; ch < 4; ch++) {
        int st = ch & 1;
        if (ch < 3) {
            load_chunk(ch + 1, st ^ 1);
            asm volatile("cp.async.wait_group 1;");
        } else {
            asm volatile("cp.async.wait_group 0;");
        }
        __syncthreads();

        uint32_t sb = smb + (uint32_t)st * STAGEB;
#pragma unroll
        for (int ks = 0; ks < 4; ks++) {
            uint32_t kso = (uint32_t)(ks * 16) * 2;
            // load ALL fragments for this ks first
            uint32_t bh[4][2], bl[4][2];
#pragma unroll
            for (int nf2 = 0; nf2 < 2; nf2++) {
                uint32_t ba = sb + 2 * TILEB + boff0 + (uint32_t)(nf2 * 16 * SPITCH) * 2 + kso;
                ldsm4(bh[nf2 * 2][0], bh[nf2 * 2][1], bh[nf2 * 2 + 1][0], bh[nf2 * 2 + 1][1], ba);
                uint32_t bb = sb + 3 * TILEB + boff0 + (uint32_t)(nf2 * 16 * SPITCH) * 2 + kso;
                ldsm4(bl[nf2 * 2][0], bl[nf2 * 2][1], bl[nf2 * 2 + 1][0], bl[nf2 * 2 + 1][1], bb);
            }
            uint32_t ah[4][4], al[4][4];
#pragma unroll
            for (int mf = 0; mf < 4; mf++) {
                uint32_t aa = sb + aoff + (uint32_t)(mf * 16 * SPITCH) * 2 + kso;
                ldsm4(ah[mf][0], ah[mf][1], ah[mf][2], ah[mf][3], aa);
                uint32_t ab = sb + TILEB + aoff + (uint32_t)(mf * 16 * SPITCH) * 2 + kso;
                ldsm4(al[mf][0], al[mf][1], al[mf][2], al[mf][3], ab);
            }
            // term-major passes: 16 independent MMAs per pass
#pragma unroll
            for (int mf = 0; mf < 4; mf++)
#pragma unroll
                for (int nf = 0; nf < 4; nf++)
                    mma16816(acc[mf][nf], ah[mf], bh[nf]);
#pragma unroll
            for (int mf = 0; mf < 4; mf++)
#pragma unroll
                for (int nf = 0; nf < 4; nf++)
                    mma16816(acc[mf][nf], ah[mf], bl[nf]);
#pragma unroll
            for (int mf = 0; mf < 4; mf++)
#pragma unroll
                for (int nf = 0; nf < 4; nf++)
                    mma16816(acc[mf][nf], al[mf], bh[nf]);
        }
        __syncthreads();
    }

    int hw0 = ntile * 128;
    if (mb < 2) {
#pragma unroll
        for (int mf = 0; mf < 4; mf++) {
            int m0 = mb * 128 + mwarp + mf * 16 + (lane >> 2);
#pragma unroll
            for (int nf = 0; nf < 4; nf++) {
                int col = hw0 + nwarp + nf * 8 + (lane & 3) * 2;
                float* o0 = g_v + (size_t)b * CDHW + (size_t)m0 * DHW + (size_t)d * HW + col;
                float* o1 = g_v + (size_t)b * CDHW + (size_t)(m0 + 8) * DHW + (size_t)d * HW + col;
                *(float2*)o0 = make_float2(acc[mf][nf][0], acc[mf][nf][1]);
                *(float2*)o1 = make_float2(acc[mf][nf][2], acc[mf][nf][3]);
            }
        }
    } else {
#pragma unroll
        for (int mf = 0; mf < 4; mf++) {
            float mlo = -3.402823466e38f, mhi = -3.402823466e38f;
#pragma unroll
            for (int nf = 0; nf < 4; nf++) {
                mlo = fmaxf(mlo, fmaxf(acc[mf][nf][0], acc[mf][nf][1]));
                mhi = fmaxf(mhi, fmaxf(acc[mf][nf][2], acc[mf][nf][3]));
            }
#pragma unroll
            for (int off = 2; off >= 1; off >>= 1) {
                mlo = fmaxf(mlo, __shfl_xor_sync(0xffffffffu, mlo, off));
                mhi = fmaxf(mhi, __shfl_xor_sync(0xffffffffu, mhi, off));
            }
            if ((lane & 3) == 0) {
                int m0 = (mb - 2) * 128 + mwarp + mf * 16 + (lane >> 2);
                atomicMaxFloat(&g_qp[sl * C + m0], mlo);
                atomicMaxFloat(&g_qp[sl * C + m0 + 8], mhi);
            }
        }
    }
}

// ---------------- offsets / attention / mixing matrix M ----------------
__launch_bounds__(256)
__global__ void k_mrow(const float* __restrict__ offs_w,
                       const float* __restrict__ offs_b,
                       const float* __restrict__ attn_w,
                       const float* __restrict__ attn_b) {
    __shared__ float sh[12][8];
    int bz = blockIdx.x;
    int c = threadIdx.x;
    float q = g_qp[(size_t)bz * C + c];

    float po[HP], pl[HP];
#pragma unroll
    for (int p = 0; p < HP; p++) {
        po[p] = q * offs_w[p * C + c];
        pl[p] = q * attn_w[p * C + c];
    }
#pragma unroll
    for (int off = 16; off >= 1; off >>= 1) {
#pragma unroll
        for (int p = 0; p < HP; p++) {
            po[p] += __shfl_xor_sync(0xffffffffu, po[p], off);
            pl[p] += __shfl_xor_sync(0xffffffffu, pl[p], off);
        }
    }
    int lane = c & 31, wid = c >> 5;
    if (lane == 0) {
#pragma unroll
        for (int p = 0; p < HP; p++) { sh[p][wid] = po[p]; sh[HP + p][wid] = pl[p]; }
    }
    __syncthreads();
    if (c == 0) {
        float offv[HP], lg[HP];
#pragma unroll
        for (int p = 0; p < HP; p++) {
            float s1 = 0.f, s2 = 0.f;
#pragma unroll
            for (int w = 0; w < 8; w++) { s1 += sh[p][w]; s2 += sh[HP + p][w]; }
            offv[p] = s1 + offs_b[p];
            lg[p]   = s2 + attn_b[p];
        }
        float mx = lg[0];
#pragma unroll
        for (int p = 1; p < HP; p++) mx = fmaxf(mx, lg[p]);
        float s = 0.f;
#pragma unroll
        for (int p = 0; p < HP; p++) { lg[p] = expf(lg[p] - mx); s += lg[p]; }
        float inv = 1.f / s;

        float row[ZS];
#pragma unroll
        for (int y = 0; y < ZS; y++) row[y] = 0.f;
#pragma unroll
        for (int p = 0; p < HP; p++) {
            float o = fminf(fmaxf(offv[p], 0.f), (float)(ZS - 1));
            float lo = floorf(o), hi = ceilf(o);
            float fr = o - lo;
            float a = lg[p] * inv;
            row[(int)lo] += a * (1.f - fr);
            row[(int)hi] += a * fr;
        }
#pragma unroll
        for (int y = 0; y < ZS; y++) g_M[bz * ZS + y] = row[y];
    }
}

// ---------------- depth mixing -> d_out, fused BN partial stats ----------------
__launch_bounds__(256)
__global__ void k_mix_stats(float* __restrict__ out) {
    __shared__ float Ms[ZS * ZS];
    __shared__ float red1[8], red2[8];
    int t = blockIdx.x * 256 + threadIdx.x;
    int b = (blockIdx.x * 256) / (C * HW);
    for (int i = threadIdx.x; i < ZS * ZS; i += 256)
        Ms[i] = g_M[b * ZS * ZS + i];
    __syncthreads();

    int rem = t % (C * HW);
    int c = rem / HW, hw = rem % HW;
    const float* base = g_v + (size_t)b * CDHW + (size_t)c * DHW + hw;
    float* ob = out + (size_t)b * CDHW + (size_t)c * DHW + hw;
    float v[ZS];
#pragma unroll
    for (int y = 0; y < ZS; y++) v[y] = base[(size_t)y * HW];
    float s1 = 0.f, s2 = 0.f;
#pragma unroll
    for (int z = 0; z < ZS; z++) {
        float a = 0.f;
#pragma unroll
        for (int y = 0; y < ZS; y++) a += Ms[z * ZS + y] * v[y];
        ob[(size_t)z * HW] = a;
        s1 += a; s2 += a * a;
    }
#pragma unroll
    for (int off = 16; off >= 1; off >>= 1) {
        s1 += __shfl_xor_sync(0xffffffffu, s1, off);
        s2 += __shfl_xor_sync(0xffffffffu, s2, off);
    }
    int lane = threadIdx.x & 31, wid = threadIdx.x >> 5;
    if (lane == 0) { red1[wid] = s1; red2[wid] = s2; }
    __syncthreads();
    if (threadIdx.x < 8) {
        s1 = red1[threadIdx.x]; s2 = red2[threadIdx.x];
#pragma unroll
        for (int off = 4; off >= 1; off >>= 1) {
            s1 += __shfl_xor_sync(0xffu, s1, off);
            s2 += __shfl_xor_sync(0xffu, s2, off);
        }
        if (threadIdx.x == 0) {
            atomicAdd(&g_sum[c], s1);
            atomicAdd(&g_sumsq[c], s2);
        }
    }
}

// ---------------- finalize BN scale/shift ----------------
__global__ void k_stats(const float* __restrict__ gamma,
                        const float* __restrict__ beta) {
    int o = threadIdx.x;
    if (o >= C) return;
    float cnt = (float)NTOT;
    float mean = g_sum[o] / cnt;
    float var = g_sumsq[o] / cnt - mean * mean;
    float inv = rsqrtf(var + 1e-5f);
    g_scale[o] = inv * gamma[o];
    g_shift[o] = beta[o] - mean * inv * gamma[o];
}

// ---------------- BN apply + residual, in place on out ----------------
__launch_bounds__(256)
__global__ void k_apply(const float* __restrict__ feat, float* __restrict__ out) {
    size_t i = ((size_t)blockIdx.x * 256 + threadIdx.x) * 4;
    if (i >= (size_t)TOT) return;
    int c = (int)((i / DHW) % C);
    float sc = g_scale[c], sh = g_shift[c];
    float4 p = *(float4*)(out + i);
    float4 f = *(const float4*)(feat + i);
    p.x = p.x * sc + sh + f.x;
    p.y = p.y * sc + sh + f.y;
    p.z = p.z * sc + sh + f.z;
    p.w = p.w * sc + sh + f.w;
    *(float4*)(out + i) = p;
}

extern "C" void kernel_launch(void* const* d_in, const int* in_sizes, int n_in,
                              void* d_out, int out_size) {
    const float* feat   = (const float*)d_in[0];
    const float* q_w    = (const float*)d_in[1];
    const float* v_w    = (const float*)d_in[2];
    const float* o_w    = (const float*)d_in[3];
    const float* offs_w = (const float*)d_in[4];
    const float* offs_b = (const float*)d_in[5];
    const float* attn_w = (const float*)d_in[6];
    const float* attn_b = (const float*)d_in[7];
    const float* gamma  = (const float*)d_in[8];
    const float* beta   = (const float*)d_in[9];
    float* out = (float*)d_out;

    cudaFuncSetAttribute(k_gemm, cudaFuncAttributeMaxDynamicSharedMemorySize, DYN_SMEM);

    k_init<<<64, 256>>>();
    k_wsplit<<<512, 256>>>(o_w, v_w, q_w);
    k_xsplit<<<4608, 256>>>(feat);
    k_gemm<<<dim3(4, 18, 64), 256, DYN_SMEM>>>();
    k_mrow<<<64, 256>>>(offs_w, offs_b, attn_w, attn_b);
    k_mix_stats<<<4608, 256>>>(out);
    k_stats<<<1, 256>>>(gamma, beta);
    k_apply<<<36864, 256>>>(feat, out);
}

// round 16
// speedup vs baseline: 1.5229x; 1.1272x over previous
#include <cuda_runtime.h>
#include <cuda_bf16.h>
#include <math.h>
#include <stdint.h>

#define B 2
#define C 256
#define ZS 32
#define HW 2304
#define DHW 73728
#define CDHW 18874368
#define TOT 37748736
#define HP 6
#define NTOT 147456
#define NROWS 147456   // B*ZS*HW

// GEMM smem: per stage 4 tiles of 128 rows x 32 bf16, padded to 40 elems (80B)/row
#define SPITCH 40
#define TILEB (128 * SPITCH * 2)     // 10240 bytes
#define STAGEB (4 * TILEB)           // 40960 bytes
#define DYN_SMEM (2 * STAGEB)        // 81920 bytes per CTA (2 CTAs/SM)

// ---------------- scratch (no allocations allowed) ----------------
__device__ float g_v[TOT];                    // u = W·x
__device__ __nv_bfloat16 g_ahi[512 * C];      // rows 0-255: o_w@v_w, 256-511: q_w
__device__ __nv_bfloat16 g_alo[512 * C];
__device__ __nv_bfloat16 g_bhi[(size_t)NROWS * C]; // x transposed (slice,hw,c)
__device__ __nv_bfloat16 g_blo[(size_t)NROWS * C];
__device__ float g_pe[ZS * C];
__device__ float g_qp[B * ZS * C];
__device__ float g_M[B * ZS * ZS];
__device__ float g_sum[C];
__device__ float g_sumsq[C];
__device__ float g_scale[C];
__device__ float g_shift[C];

__device__ __forceinline__ uint32_t smem_u32(const void* p) {
    uint32_t a;
    asm("{ .reg .u64 t; cvta.to.shared.u64 t, %1; cvt.u32.u64 %0, t; }" : "=r"(a) : "l"(p));
    return a;
}

__device__ __forceinline__ void cpasync16(uint32_t dst, const void* src) {
    asm volatile("cp.async.cg.shared.global [%0], [%1], 16;" :: "r"(dst), "l"(src));
}

__device__ __forceinline__ void ldsm4(uint32_t& r0, uint32_t& r1, uint32_t& r2, uint32_t& r3,
                                      uint32_t addr) {
    asm volatile("ldmatrix.sync.aligned.m8n8.x4.shared.b16 {%0,%1,%2,%3}, [%4];"
                 : "=r"(r0), "=r"(r1), "=r"(r2), "=r"(r3) : "r"(addr));
}

__device__ __forceinline__ void mma16816(float* d, const uint32_t* a, const uint32_t* b) {
    asm volatile(
        "mma.sync.aligned.m16n8k16.row.col.f32.bf16.bf16.f32 "
        "{%0,%1,%2,%3}, {%4,%5,%6,%7}, {%8,%9}, {%0,%1,%2,%3};"
        : "+f"(d[0]), "+f"(d[1]), "+f"(d[2]), "+f"(d[3])
        : "r"(a[0]), "r"(a[1]), "r"(a[2]), "r"(a[3]), "r"(b[0]), "r"(b[1]));
}

__device__ __forceinline__ void atomicMaxFloat(float* addr, float val) {
    int* ia = (int*)addr;
    int old = *ia;
    while (__int_as_float(old) < val) {
        int prev = atomicCAS(ia, old, __float_as_int(val));
        if (prev == old) break;
        old = prev;
    }
}

// ---------------- init ----------------
__global__ void k_init() {
    int i = blockIdx.x * blockDim.x + threadIdx.x;
    if (i < B * ZS * C) g_qp[i] = -3.402823466e38f;
    if (i < ZS * C) {
        int d = i / C, c = i % C;
        int ii = c >> 1;
        float ang = (float)d * expf(-0.0719557841560637f * (float)ii);
        g_pe[i] = (c & 1) ? cosf(ang) : sinf(ang);
    }
    if (i < C) { g_sum[i] = 0.f; g_sumsq[i] = 0.f; }
}

// ---------------- fold W = o_w@v_w, stack q_w, split bf16 hi/lo ----------------
__launch_bounds__(256)
__global__ void k_wsplit(const float* __restrict__ o_w, const float* __restrict__ v_w,
                         const float* __restrict__ q_w) {
    __shared__ float orow[C];
    int r = blockIdx.x, c = threadIdx.x;
    float val;
    if (r < 256) {
        orow[c] = o_w[r * C + c];
        __syncthreads();
        float acc = 0.f;
#pragma unroll 8
        for (int k = 0; k < C; k++) acc += orow[k] * v_w[k * C + c];
        val = acc;
    } else {
        val = q_w[(r - 256) * C + c];
    }
    __nv_bfloat16 h = __float2bfloat16(val);
    g_ahi[r * C + c] = h;
    g_alo[r * C + c] = __float2bfloat16(val - __bfloat162float(h));
}

// ---------------- x = feat + pe, transpose to (slice,hw,c), split hi/lo ----------------
__launch_bounds__(256)
__global__ void k_xsplit(const float* __restrict__ feat) {
    __shared__ __nv_bfloat16 shi[C][33];
    __shared__ __nv_bfloat16 slo[C][33];
    int blk = blockIdx.x;
    int sl = blk / 72, tile = blk % 72;
    int b = sl >> 5, d = sl & 31;
    int hw0 = tile * 32;
    int t = threadIdx.x, lane = t & 31, w = t >> 5;
    const float* fb = feat + (size_t)b * CDHW + (size_t)d * HW + hw0 + lane;
#pragma unroll 4
    for (int cc = 0; cc < 32; cc++) {
        int c = cc * 8 + w;
        float v = fb[(size_t)c * DHW] + g_pe[d * C + c];
        __nv_bfloat16 h = __float2bfloat16(v);
        shi[c][lane] = h;
        slo[c][lane] = __float2bfloat16(v - __bfloat162float(h));
    }
    __syncthreads();
    int row = t >> 3, seg = t & 7;
    size_t n = (size_t)sl * HW + hw0 + row;
#pragma unroll
    for (int q = 0; q < 4; q++) {
        int c0 = (q * 8 + seg) * 8;
        union { __nv_bfloat16 v[8]; uint4 u; } ph, pl;
#pragma unroll
        for (int j = 0; j < 8; j++) { ph.v[j] = shi[c0 + j][row]; pl.v[j] = slo[c0 + j][row]; }
        *(uint4*)(g_bhi + n * C + c0) = ph.u;
        *(uint4*)(g_blo + n * C + c0) = pl.u;
    }
}

// ---------------- bf16 mma.sync GEMM, cp.async 2-stage, 2 CTAs/SM ----------------
// grid (4 mb, 18 ntiles, 64 slices), 256 thr, warp tile 64x32, K-chunk 32.
// mb 0,1 -> u (g_v); mb 2,3 -> q (max into g_qp).
__global__ void __launch_bounds__(256, 2) k_gemm() {
    extern __shared__ char sm[];
    uint32_t smb = smem_u32(sm);

    int tid = threadIdx.x, lane = tid & 31, wid = tid >> 5;
    int mb = blockIdx.x, ntile = blockIdx.y, sl = blockIdx.z;
    int b = sl >> 5, d = sl & 31;
    int mwarp = (wid >> 2) * 64;
    int nwarp = (wid & 3) * 32;

    size_t arow0 = (size_t)mb * 128;
    size_t nrow0 = (size_t)sl * HW + (size_t)ntile * 128;

    float acc[4][4][4];
#pragma unroll
    for (int mf = 0; mf < 4; mf++)
#pragma unroll
        for (int nf = 0; nf < 4; nf++)
#pragma unroll
            for (int e = 0; e < 4; e++) acc[mf][nf][e] = 0.f;

    // ldmatrix source byte offsets within a tile
    uint32_t aoff = (uint32_t)((mwarp + (lane & 15)) * SPITCH + ((lane >> 4) << 3)) * 2;
    uint32_t boff0 = (uint32_t)((nwarp + (lane & 7) + ((lane >> 4) << 3)) * SPITCH
                                + (((lane >> 3) & 1) << 3)) * 2;

    // async chunk loader: chunk ch (k0 = ch*32) into stage st
    auto load_chunk = [&](int ch, int st) {
        int k0 = ch * 32;
        uint32_t sb = smb + (uint32_t)st * STAGEB;
#pragma unroll
        for (int i = 0; i < 2; i++) {
            int idx = tid + 256 * i;
            int r = idx >> 2, cc = idx & 3;
            uint32_t so = (uint32_t)(r * SPITCH + cc * 8) * 2;
            const __nv_bfloat16* pa = g_ahi + (arow0 + r) * C + k0 + cc * 8;
            const __nv_bfloat16* pb = g_alo + (arow0 + r) * C + k0 + cc * 8;
            const __nv_bfloat16* pc = g_bhi + (nrow0 + r) * C + k0 + cc * 8;
            const __nv_bfloat16* pd = g_blo + (nrow0 + r) * C + k0 + cc * 8;
            cpasync16(sb + so, pa);
            cpasync16(sb + TILEB + so, pb);
            cpasync16(sb + 2 * TILEB + so, pc);
            cpasync16(sb + 3 * TILEB + so, pd);
        }
        asm volatile("cp.async.commit_group;");
    };

    load_chunk(0, 0);

    for (int ch = 0; ch < 8; ch++) {
        int st = ch & 1;
        if (ch < 7) {
            load_chunk(ch + 1, st ^ 1);
            asm volatile("cp.async.wait_group 1;");
        } else {
            asm volatile("cp.async.wait_group 0;");
        }
        __syncthreads();

        uint32_t sb = smb + (uint32_t)st * STAGEB;
#pragma unroll
        for (int ks = 0; ks < 2; ks++) {
            uint32_t kso = (uint32_t)(ks * 16) * 2;
            // load ALL fragments for this ks first
            uint32_t bh[4][2], bl[4][2];
#pragma unroll
            for (int nf2 = 0; nf2 < 2; nf2++) {
                uint32_t ba = sb + 2 * TILEB + boff0 + (uint32_t)(nf2 * 16 * SPITCH) * 2 + kso;
                ldsm4(bh[nf2 * 2][0], bh[nf2 * 2][1], bh[nf2 * 2 + 1][0], bh[nf2 * 2 + 1][1], ba);
                uint32_t bb = sb + 3 * TILEB + boff0 + (uint32_t)(nf2 * 16 * SPITCH) * 2 + kso;
                ldsm4(bl[nf2 * 2][0], bl[nf2 * 2][1], bl[nf2 * 2 + 1][0], bl[nf2 * 2 + 1][1], bb);
            }
            uint32_t ah[4][4], al[4][4];
#pragma unroll
            for (int mf = 0; mf < 4; mf++) {
                uint32_t aa = sb + aoff + (uint32_t)(mf * 16 * SPITCH) * 2 + kso;
                ldsm4(ah[mf][0], ah[mf][1], ah[mf][2], ah[mf][3], aa);
                uint32_t ab = sb + TILEB + aoff + (uint32_t)(mf * 16 * SPITCH) * 2 + kso;
                ldsm4(al[mf][0], al[mf][1], al[mf][2], al[mf][3], ab);
            }
            // term-major passes: 16 independent MMAs per pass
#pragma unroll
            for (int mf = 0; mf < 4; mf++)
#pragma unroll
                for (int nf = 0; nf < 4; nf++)
                    mma16816(acc[mf][nf], ah[mf], bh[nf]);
#pragma unroll
            for (int mf = 0; mf < 4; mf++)
#pragma unroll
                for (int nf = 0; nf < 4; nf++)
                    mma16816(acc[mf][nf], ah[mf], bl[nf]);
#pragma unroll
            for (int mf = 0; mf < 4; mf++)
#pragma unroll
                for (int nf = 0; nf < 4; nf++)
                    mma16816(acc[mf][nf], al[mf], bh[nf]);
        }
        __syncthreads();
    }

    int hw0 = ntile * 128;
    if (mb < 2) {
#pragma unroll
        for (int mf = 0; mf < 4; mf++) {
            int m0 = mb * 128 + mwarp + mf * 16 + (lane >> 2);
#pragma unroll
            for (int nf = 0; nf < 4; nf++) {
                int col = hw0 + nwarp + nf * 8 + (lane & 3) * 2;
                float* o0 = g_v + (size_t)b * CDHW + (size_t)m0 * DHW + (size_t)d * HW + col;
                float* o1 = g_v + (size_t)b * CDHW + (size_t)(m0 + 8) * DHW + (size_t)d * HW + col;
                *(float2*)o0 = make_float2(acc[mf][nf][0], acc[mf][nf][1]);
                *(float2*)o1 = make_float2(acc[mf][nf][2], acc[mf][nf][3]);
            }
        }
    } else {
#pragma unroll
        for (int mf = 0; mf < 4; mf++) {
            float mlo = -3.402823466e38f, mhi = -3.402823466e38f;
#pragma unroll
            for (int nf = 0; nf < 4; nf++) {
                mlo = fmaxf(mlo, fmaxf(acc[mf][nf][0], acc[mf][nf][1]));
                mhi = fmaxf(mhi, fmaxf(acc[mf][nf][2], acc[mf][nf][3]));
            }
#pragma unroll
            for (int off = 2; off >= 1; off >>= 1) {
                mlo = fmaxf(mlo, __shfl_xor_sync(0xffffffffu, mlo, off));
                mhi = fmaxf(mhi, __shfl_xor_sync(0xffffffffu, mhi, off));
            }
            if ((lane & 3) == 0) {
                int m0 = (mb - 2) * 128 + mwarp + mf * 16 + (lane >> 2);
                atomicMaxFloat(&g_qp[sl * C + m0], mlo);
                atomicMaxFloat(&g_qp[sl * C + m0 + 8], mhi);
            }
        }
    }
}

// ---------------- offsets / attention / mixing matrix M ----------------
__launch_bounds__(256)
__global__ void k_mrow(const float* __restrict__ offs_w,
                       const float* __restrict__ offs_b,
                       const float* __restrict__ attn_w,
                       const float* __restrict__ attn_b) {
    __shared__ float sh[12][8];
    int bz = blockIdx.x;
    int c = threadIdx.x;
    float q = g_qp[(size_t)bz * C + c];

    float po[HP], pl[HP];
#pragma unroll
    for (int p = 0; p < HP; p++) {
        po[p] = q * offs_w[p * C + c];
        pl[p] = q * attn_w[p * C + c];
    }
#pragma unroll
    for (int off = 16; off >= 1; off >>= 1) {
#pragma unroll
        for (int p = 0; p < HP; p++) {
            po[p] += __shfl_xor_sync(0xffffffffu, po[p], off);
            pl[p] += __shfl_xor_sync(0xffffffffu, pl[p], off);
        }
    }
    int lane = c & 31, wid = c >> 5;
    if (lane == 0) {
#pragma unroll
        for (int p = 0; p < HP; p++) { sh[p][wid] = po[p]; sh[HP + p][wid] = pl[p]; }
    }
    __syncthreads();
    if (c == 0) {
        float offv[HP], lg[HP];
#pragma unroll
        for (int p = 0; p < HP; p++) {
            float s1 = 0.f, s2 = 0.f;
#pragma unroll
            for (int w = 0; w < 8; w++) { s1 += sh[p][w]; s2 += sh[HP + p][w]; }
            offv[p] = s1 + offs_b[p];
            lg[p]   = s2 + attn_b[p];
        }
        float mx = lg[0];
#pragma unroll
        for (int p = 1; p < HP; p++) mx = fmaxf(mx, lg[p]);
        float s = 0.f;
#pragma unroll
        for (int p = 0; p < HP; p++) { lg[p] = expf(lg[p] - mx); s += lg[p]; }
        float inv = 1.f / s;

        float row[ZS];
#pragma unroll
        for (int y = 0; y < ZS; y++) row[y] = 0.f;
#pragma unroll
        for (int p = 0; p < HP; p++) {
            float o = fminf(fmaxf(offv[p], 0.f), (float)(ZS - 1));
            float lo = floorf(o), hi = ceilf(o);
            float fr = o - lo;
            float a = lg[p] * inv;
            row[(int)lo] += a * (1.f - fr);
            row[(int)hi] += a * fr;
        }
#pragma unroll
        for (int y = 0; y < ZS; y++) g_M[bz * ZS + y] = row[y];
    }
}

// ---------------- depth mixing -> d_out, fused BN partial stats ----------------
__launch_bounds__(256)
__global__ void k_mix_stats(float* __restrict__ out) {
    __shared__ float Ms[ZS * ZS];
    __shared__ float red1[8], red2[8];
    int t = blockIdx.x * 256 + threadIdx.x;
    int b = (blockIdx.x * 256) / (C * HW);
    for (int i = threadIdx.x; i < ZS * ZS; i += 256)
        Ms[i] = g_M[b * ZS * ZS + i];
    __syncthreads();

    int rem = t % (C * HW);
    int c = rem / HW, hw = rem % HW;
    const float* base = g_v + (size_t)b * CDHW + (size_t)c * DHW + hw;
    float* ob = out + (size_t)b * CDHW + (size_t)c * DHW + hw;
    float v[ZS];
#pragma unroll
    for (int y = 0; y < ZS; y++) v[y] = base[(size_t)y * HW];
    float s1 = 0.f, s2 = 0.f;
#pragma unroll
    for (int z = 0; z < ZS; z++) {
        float a = 0.f;
#pragma unroll
        for (int y = 0; y < ZS; y++) a += Ms[z * ZS + y] * v[y];
        ob[(size_t)z * HW] = a;
        s1 += a; s2 += a * a;
    }
#pragma unroll
    for (int off = 16; off >= 1; off >>= 1) {
        s1 += __shfl_xor_sync(0xffffffffu, s1, off);
        s2 += __shfl_xor_sync(0xffffffffu, s2, off);
    }
    int lane = threadIdx.x & 31, wid = threadIdx.x >> 5;
    if (lane == 0) { red1[wid] = s1; red2[wid] = s2; }
    __syncthreads();
    if (threadIdx.x < 8) {
        s1 = red1[threadIdx.x]; s2 = red2[threadIdx.x];
#pragma unroll
        for (int off = 4; off >= 1; off >>= 1) {
            s1 += __shfl_xor_sync(0xffu, s1, off);
            s2 += __shfl_xor_sync(0xffu, s2, off);
        }
        if (threadIdx.x == 0) {
            atomicAdd(&g_sum[c], s1);
            atomicAdd(&g_sumsq[c], s2);
        }
    }
}

// ---------------- finalize BN scale/shift ----------------
__global__ void k_stats(const float* __restrict__ gamma,
                        const float* __restrict__ beta) {
    int o = threadIdx.x;
    if (o >= C) return;
    float cnt = (float)NTOT;
    float mean = g_sum[o] / cnt;
    float var = g_sumsq[o] / cnt - mean * mean;
    float inv = rsqrtf(var + 1e-5f);
    g_scale[o] = inv * gamma[o];
    g_shift[o] = beta[o] - mean * inv * gamma[o];
}

// ---------------- BN apply + residual, in place on out ----------------
__launch_bounds__(256)
__global__ void k_apply(const float* __restrict__ feat, float* __restrict__ out) {
    size_t i = ((size_t)blockIdx.x * 256 + threadIdx.x) * 4;
    if (i >= (size_t)TOT) return;
    int c = (int)((i / DHW) % C);
    float sc = g_scale[c], sh = g_shift[c];
    float4 p = *(float4*)(out + i);
    float4 f = *(const float4*)(feat + i);
    p.x = p.x * sc + sh + f.x;
    p.y = p.y * sc + sh + f.y;
    p.z = p.z * sc + sh + f.z;
    p.w = p.w * sc + sh + f.w;
    *(float4*)(out + i) = p;
}

extern "C" void kernel_launch(void* const* d_in, const int* in_sizes, int n_in,
                              void* d_out, int out_size) {
    const float* feat   = (const float*)d_in[0];
    const float* q_w    = (const float*)d_in[1];
    const float* v_w    = (const float*)d_in[2];
    const float* o_w    = (const float*)d_in[3];
    const float* offs_w = (const float*)d_in[4];
    const float* offs_b = (const float*)d_in[5];
    const float* attn_w = (const float*)d_in[6];
    const float* attn_b = (const float*)d_in[7];
    const float* gamma  = (const float*)d_in[8];
    const float* beta   = (const float*)d_in[9];
    float* out = (float*)d_out;

    cudaFuncSetAttribute(k_gemm, cudaFuncAttributeMaxDynamicSharedMemorySize, DYN_SMEM);

    k_init<<<64, 256>>>();
    k_wsplit<<<512, 256>>>(o_w, v_w, q_w);
    k_xsplit<<<4608, 256>>>(feat);
    k_gemm<<<dim3(4, 18, 64), 256, DYN_SMEM>>>();
    k_mrow<<<64, 256>>>(offs_w, offs_b, attn_w, attn_b);
    k_mix_stats<<<4608, 256>>>(out);
    k_stats<<<1, 256>>>(gamma, beta);
    k_apply<<<36864, 256>>>(feat, out);
}